// round 2
// baseline (speedup 1.0000x reference)
#include <cuda_runtime.h>
#include <cstdint>

// ============================ problem sizes ============================
#define BATCH   8192
#define INDIM   1024
#define OUTDIM  1024
#define DEG1    9
#define KDIM    (INDIM * DEG1)      // 9216
#define TM      128                 // CTA M tile
#define TN      256                 // CTA N tile
#define KC      32                  // K chunk per pipeline stage
#define NITER   (KDIM / KC)         // 288  (= 32 i-blocks x 9)
#define NTHREADS 256

// SMEM strides (floats), padded for bank-conflict-free fragment loads
#define AST  36                     // A row stride (128 rows x 36)
#define BST  36                     // B row stride (256 rows x 36)
#define TST  36                     // t row stride (128 rows x 36)

// __device__ scratch (static: allocation-guard safe)
__device__ float g_Bt[(size_t)OUTDIM * KDIM];   // Bt[o][i*9+d], tf32-rounded bits
__device__ float g_t[(size_t)BATCH * INDIM];    // clip(tanh(x))

// ============================ helpers ==================================
__device__ __forceinline__ uint32_t f32_to_tf32(float x) {
    uint32_t u;
    asm("cvt.rna.tf32.f32 %0, %1;" : "=r"(u) : "f"(x));
    return u;
}

__device__ __forceinline__ void cp_async16(uint32_t smem_dst, const void* gsrc) {
    asm volatile("cp.async.cg.shared.global [%0], [%1], 16;"
                 :: "r"(smem_dst), "l"(gsrc) : "memory");
}
__device__ __forceinline__ void cp_commit() {
    asm volatile("cp.async.commit_group;" ::: "memory");
}
__device__ __forceinline__ void cp_wait0() {
    asm volatile("cp.async.wait_group 0;" ::: "memory");
}

__device__ __forceinline__ uint32_t smem_u32(const void* p) {
    uint32_t a;
    asm("{ .reg .u64 t; cvta.to.shared.u64 t, %1; cvt.u32.u64 %0, t; }" : "=r"(a) : "l"(p));
    return a;
}

// mma.sync m16n8k8 row.col f32.tf32.tf32.f32  (sm_80+, works on plain compute_103)
__device__ __forceinline__ void mma8(float* c, const uint32_t* a, const uint32_t* b) {
    asm volatile(
        "mma.sync.aligned.m16n8k8.row.col.f32.tf32.tf32.f32 "
        "{%0,%1,%2,%3}, {%4,%5,%6,%7}, {%8,%9}, {%0,%1,%2,%3};"
        : "+f"(c[0]), "+f"(c[1]), "+f"(c[2]), "+f"(c[3])
        : "r"(a[0]), "r"(a[1]), "r"(a[2]), "r"(a[3]), "r"(b[0]), "r"(b[1]));
}

// ======================= prep: t = clip(tanh(x)) =======================
__global__ __launch_bounds__(256)
void prep_t_kernel(const float* __restrict__ x) {
    size_t i4 = (size_t)blockIdx.x * 256 + threadIdx.x;   // float4 index
    const float4* src = (const float4*)x;
    float4* dst = (float4*)g_t;
    float4 v = src[i4];
    float4 r;
    r.x = fminf(fmaxf(tanhf(v.x), -0.999f), 0.999f);
    r.y = fminf(fmaxf(tanhf(v.y), -0.999f), 0.999f);
    r.z = fminf(fmaxf(tanhf(v.z), -0.999f), 0.999f);
    r.w = fminf(fmaxf(tanhf(v.w), -0.999f), 0.999f);
    dst[i4] = r;
}

// ======================= prep: C[i,o,d] -> Bt[o, i*9+d] (tf32) =========
__global__ __launch_bounds__(256)
void prep_Bt_kernel(const float* __restrict__ C) {
    int idx = blockIdx.x * 256 + threadIdx.x;   // over INDIM*OUTDIM
    int i = idx >> 10;
    int o = idx & 1023;
    const float* src = C + (size_t)i * (OUTDIM * DEG1) + (size_t)o * DEG1;
    uint32_t* dst = (uint32_t*)(g_Bt + (size_t)o * KDIM + (size_t)i * DEG1);
#pragma unroll
    for (int d = 0; d < DEG1; d++) dst[d] = f32_to_tf32(src[d]);
}

// ============================ main GEMM ================================
__global__ __launch_bounds__(NTHREADS, 1)
void cheby_gemm_kernel(float* __restrict__ out) {
    __shared__ uint32_t As[2][TM * AST];      // 2 x 18,432 B
    __shared__ uint32_t Bs[2][TN * BST];      // 2 x 36,864 B
    __shared__ float    Ts[TM * TST];         // 18,432 B

    const int tid  = threadIdx.x;
    const int wid  = tid >> 5;
    const int lane = tid & 31;
    const int gid  = lane >> 2;     // 0..7
    const int tg   = lane & 3;      // 0..3
    const int warp_m = wid & 1;     // 2 warps along M (64 each)
    const int warp_n = wid >> 1;    // 4 warps along N (64 each)
    const int m0 = blockIdx.x * TM;
    const int n0 = blockIdx.y * TN;

    // producer mapping: each thread owns half a row of the A/t tiles
    const int pr = tid >> 1;        // row 0..127
    const int ph = tid & 1;         // half 0/1 (16 k's each)

    float acc[4][8][4];
#pragma unroll
    for (int mf = 0; mf < 4; mf++)
#pragma unroll
        for (int nf = 0; nf < 8; nf++)
#pragma unroll
            for (int q = 0; q < 4; q++) acc[mf][nf][q] = 0.0f;

    // ---- prologue: kick B[0] ----
    {
        const float* src = g_Bt + (size_t)(n0 + tid) * KDIM;   // k0 = 0
        uint32_t dst = smem_u32(&Bs[0][tid * BST]);
#pragma unroll
        for (int q = 0; q < 8; q++) cp_async16(dst + q * 16, src + q * 4);
        cp_commit();
    }

    for (int ib = 0; ib < INDIM / 32; ib++) {          // 32 i-blocks
        // ---- refresh t tile for this i-block ----
        __syncthreads();                                // prior produce readers done
        {
            int i0 = ib * 32;
            const float4* src = (const float4*)(g_t + (size_t)(m0 + pr) * INDIM + i0 + ph * 16);
            float4* dstv = (float4*)&Ts[pr * TST + ph * 16];
#pragma unroll
            for (int q = 0; q < 4; q++) dstv[q] = src[q];
        }
        __syncthreads();

#pragma unroll 1
        for (int jj = 0; jj < 9; jj++) {
            const int j = ib * 9 + jj;
            const int s = j & 1;

            // ---- produce A[s]: Chebyshev recurrence, 16 k's per thread ----
            {
                const float* trow = &Ts[pr * TST];
                int idx = jj * 32 + ph * 16;           // k offset within i-block
                int il  = idx / 9;
                int d   = idx % 9;
                float t = trow[il];
                float Ta, Tb;
                if (d == 0) { Ta = 1.0f; Tb = 0.0f; }
                else {
                    float u0 = 1.0f, u1 = t;
#pragma unroll 1
                    for (int e = 2; e <= d; e++) { float u2 = fmaf(2.0f * t, u1, -u0); u0 = u1; u1 = u2; }
                    Ta = u1; Tb = u0;
                }
                uint32_t vals[16];
#pragma unroll
                for (int c = 0; c < 16; c++) {
                    vals[c] = f32_to_tf32(Ta);
                    d++;
                    if (d == DEG1) {
                        d = 0; il++;
                        if (il < 32) t = trow[il];
                        Ta = 1.0f; Tb = 0.0f;
                    } else if (d == 1) {
                        Tb = Ta; Ta = t;
                    } else {
                        float tn = fmaf(2.0f * t, Ta, -Tb); Tb = Ta; Ta = tn;
                    }
                }
                uint4* dstv = (uint4*)&As[s][pr * AST + ph * 16];
#pragma unroll
                for (int q = 0; q < 4; q++)
                    dstv[q] = make_uint4(vals[4*q], vals[4*q+1], vals[4*q+2], vals[4*q+3]);
            }

            // ---- B[s] arrived; all consumers of stage s^1 are done ----
            cp_wait0();
            __syncthreads();

            // ---- prefetch B[j+1] into stage s^1 ----
            if (j + 1 < NITER) {
                int k0 = (j + 1) * KC;
                const float* src = g_Bt + (size_t)(n0 + tid) * KDIM + k0;
                uint32_t dst = smem_u32(&Bs[s ^ 1][tid * BST]);
#pragma unroll
                for (int q = 0; q < 8; q++) cp_async16(dst + q * 16, src + q * 4);
            }
            cp_commit();

            // ---- consume: 128 mma per warp ----
            const uint32_t* A_ = As[s];
            const uint32_t* B_ = Bs[s];
#pragma unroll
            for (int ks = 0; ks < 4; ks++) {
                const int kk = ks * 8;
                uint32_t a[4][4];
#pragma unroll
                for (int mf = 0; mf < 4; mf++) {
                    int r0 = warp_m * 64 + mf * 16 + gid;
                    a[mf][0] = A_[r0 * AST + kk + tg];
                    a[mf][1] = A_[(r0 + 8) * AST + kk + tg];
                    a[mf][2] = A_[r0 * AST + kk + tg + 4];
                    a[mf][3] = A_[(r0 + 8) * AST + kk + tg + 4];
                }
#pragma unroll
                for (int nf = 0; nf < 8; nf++) {
                    int nn = warp_n * 64 + nf * 8 + gid;
                    uint32_t b[2];
                    b[0] = B_[nn * BST + kk + tg];
                    b[1] = B_[nn * BST + kk + tg + 4];
#pragma unroll
                    for (int mf = 0; mf < 4; mf++)
                        mma8(acc[mf][nf], a[mf], b);
                }
            }
        }
    }

    // ---- epilogue: write D ----
#pragma unroll
    for (int mf = 0; mf < 4; mf++) {
        int row = m0 + warp_m * 64 + mf * 16 + gid;
#pragma unroll
        for (int nf = 0; nf < 8; nf++) {
            int col = n0 + warp_n * 64 + nf * 8 + tg * 2;
            float2* p0 = (float2*)(out + (size_t)row * OUTDIM + col);
            float2* p1 = (float2*)(out + (size_t)(row + 8) * OUTDIM + col);
            *p0 = make_float2(acc[mf][nf][0], acc[mf][nf][1]);
            *p1 = make_float2(acc[mf][nf][2], acc[mf][nf][3]);
        }
    }
}

// ============================ host launch ==============================
extern "C" void kernel_launch(void* const* d_in, const int* in_sizes, int n_in,
                              void* d_out, int out_size) {
    const float* x;
    const float* C;
    if (in_sizes[0] == BATCH * INDIM) { x = (const float*)d_in[0]; C = (const float*)d_in[1]; }
    else                              { x = (const float*)d_in[1]; C = (const float*)d_in[0]; }
    float* out = (float*)d_out;

    prep_t_kernel<<<(BATCH * INDIM) / (256 * 4), 256>>>(x);
    prep_Bt_kernel<<<(INDIM * OUTDIM) / 256, 256>>>(C);

    dim3 grid(BATCH / TM, OUTDIM / TN, 1);   // 64 x 4 = 256 CTAs
    cheby_gemm_kernel<<<grid, NTHREADS>>>(out);
}

// round 3
// speedup vs baseline: 1.5980x; 1.5980x over previous
#include <cuda_runtime.h>
#include <cstdint>

// ============================ problem sizes ============================
#define BATCH   8192
#define INDIM   1024
#define OUTDIM  1024
#define DEG1    9
#define CK      (INDIM * DEG1)      // 9216 (coeff K incl. d=0)
#define KD2     (INDIM * 8)         // 8192 (GEMM K, d=1..8; d=0 folded into bias)
#define TM      128                 // CTA M tile
#define TN      128                 // CTA N tile
#define KC      32                  // K chunk per stage = 4 inputs x 8 degrees
#define NITER   (KD2 / KC)          // 256
#define NTHREADS 256

#define AST  36                     // A row stride (words): conflict-free frags
#define BST  36                     // B row stride
#define TST  36                     // t row stride (float4-aligned, 2-way worst)

// __device__ scratch (static: allocation-guard safe)
__device__ float g_Bt[(size_t)OUTDIM * KD2];    // Bt[o][i*8+(d-1)], tf32 bits
__device__ float g_t[(size_t)BATCH * INDIM];    // clip(tanh(x))
__device__ float g_bias[OUTDIM];                // sum_i C[i][o][0]

// ============================ helpers ==================================
__device__ __forceinline__ uint32_t f32_to_tf32(float x) {
    uint32_t u;
    asm("cvt.rna.tf32.f32 %0, %1;" : "=r"(u) : "f"(x));
    return u;
}
__device__ __forceinline__ void cp_async16(uint32_t smem_dst, const void* gsrc) {
    asm volatile("cp.async.cg.shared.global [%0], [%1], 16;"
                 :: "r"(smem_dst), "l"(gsrc) : "memory");
}
__device__ __forceinline__ void cp_commit() {
    asm volatile("cp.async.commit_group;" ::: "memory");
}
__device__ __forceinline__ void cp_wait0() {
    asm volatile("cp.async.wait_group 0;" ::: "memory");
}
__device__ __forceinline__ uint32_t smem_u32(const void* p) {
    uint32_t a;
    asm("{ .reg .u64 t; cvta.to.shared.u64 t, %1; cvt.u32.u64 %0, t; }" : "=r"(a) : "l"(p));
    return a;
}
// mma.sync m16n8k8 row.col f32.tf32.tf32.f32 (sm_80+, plain target OK)
__device__ __forceinline__ void mma8(float* c, const uint32_t* a, const uint32_t* b) {
    asm volatile(
        "mma.sync.aligned.m16n8k8.row.col.f32.tf32.tf32.f32 "
        "{%0,%1,%2,%3}, {%4,%5,%6,%7}, {%8,%9}, {%0,%1,%2,%3};"
        : "+f"(c[0]), "+f"(c[1]), "+f"(c[2]), "+f"(c[3])
        : "r"(a[0]), "r"(a[1]), "r"(a[2]), "r"(a[3]), "r"(b[0]), "r"(b[1]));
}

// ======================= prep: t = clip(tanh(x)) =======================
__global__ __launch_bounds__(256)
void prep_t_kernel(const float* __restrict__ x) {
    size_t i4 = (size_t)blockIdx.x * 256 + threadIdx.x;
    const float4* src = (const float4*)x;
    float4* dst = (float4*)g_t;
    float4 v = src[i4];
    float4 r;
    r.x = fminf(fmaxf(tanhf(v.x), -0.999f), 0.999f);
    r.y = fminf(fmaxf(tanhf(v.y), -0.999f), 0.999f);
    r.z = fminf(fmaxf(tanhf(v.z), -0.999f), 0.999f);
    r.w = fminf(fmaxf(tanhf(v.w), -0.999f), 0.999f);
    dst[i4] = r;
}

// ============ prep: C[i,o,d>=1] -> Bt[o, i*8+d-1] (tf32) ===============
__global__ __launch_bounds__(256)
void prep_Bt_kernel(const float* __restrict__ C) {
    int idx = blockIdx.x * 256 + threadIdx.x;   // over INDIM*OUTDIM
    int i = idx >> 10;
    int o = idx & 1023;
    const float* src = C + (size_t)i * (OUTDIM * DEG1) + (size_t)o * DEG1;
    uint32_t* dst = (uint32_t*)(g_Bt + (size_t)o * KD2 + (size_t)i * 8);
#pragma unroll
    for (int d = 1; d < DEG1; d++) dst[d - 1] = f32_to_tf32(src[d]);
}

// ============ prep: bias[o] = sum_i C[i,o,0] (T_0 == 1) ================
__global__ __launch_bounds__(256)
void prep_bias_kernel(const float* __restrict__ C) {
    __shared__ float red[256];
    int o = blockIdx.x;
    int tid = threadIdx.x;
    float s = 0.0f;
#pragma unroll
    for (int i = tid; i < INDIM; i += 256)
        s += C[(size_t)i * (OUTDIM * DEG1) + (size_t)o * DEG1];
    red[tid] = s;
    __syncthreads();
#pragma unroll
    for (int w = 128; w > 0; w >>= 1) {
        if (tid < w) red[tid] += red[tid + w];
        __syncthreads();
    }
    if (tid == 0) g_bias[o] = red[0];
}

// ============================ main GEMM ================================
__global__ __launch_bounds__(NTHREADS, 2)
void cheby_gemm_kernel(float* __restrict__ out) {
    __shared__ uint32_t As[2][TM * AST];      // 2 x 18,432 B
    __shared__ uint32_t Bs[2][TN * BST];      // 2 x 18,432 B
    __shared__ float    Ts[TM * TST];         // 18,432 B   (total ~90 KB)

    const int tid  = threadIdx.x;
    const int wid  = tid >> 5;
    const int lane = tid & 31;
    const int gid  = lane >> 2;     // 0..7
    const int tg   = lane & 3;      // 0..3
    const int warp_m = wid & 1;     // 2 warps along M (64 rows each)
    const int warp_n = wid >> 1;    // 4 warps along N (32 cols each)
    const int m0 = blockIdx.x * TM;
    const int n0 = blockIdx.y * TN;

    const int pr = tid >> 1;        // producer/copier row 0..127
    const int ph = tid & 1;         // half (16 k's / 16 floats)

    float acc[4][4][4];
#pragma unroll
    for (int mf = 0; mf < 4; mf++)
#pragma unroll
        for (int nf = 0; nf < 4; nf++)
#pragma unroll
            for (int q = 0; q < 4; q++) acc[mf][nf][q] = 0.0f;

    // ---- prologue: kick B[0] (128 rows x 32 floats) ----
    {
        const float* src = g_Bt + (size_t)(n0 + pr) * KD2 + ph * 16;
        uint32_t dst = smem_u32(&Bs[0][pr * BST + ph * 16]);
#pragma unroll
        for (int q = 0; q < 4; q++) cp_async16(dst + q * 16, src + q * 4);
        cp_commit();
    }

    for (int ib = 0; ib < INDIM / 32; ib++) {          // 32 i-blocks
        __syncthreads();                                // Ts readers done
        {
            const float4* src = (const float4*)(g_t + (size_t)(m0 + pr) * INDIM + ib * 32 + ph * 16);
            float4* dstv = (float4*)&Ts[pr * TST + ph * 16];
#pragma unroll
            for (int q = 0; q < 4; q++) dstv[q] = src[q];
        }
        __syncthreads();

#pragma unroll 1
        for (int jj = 0; jj < 8; jj++) {
            const int j = ib * 8 + jj;
            const int s = j & 1;

            // ---- produce A[s]: 2 inputs x degrees 1..8 per thread ----
            {
                const int il0 = jj * 4 + ph * 2;
                uint32_t vals[16];
#pragma unroll
                for (int e = 0; e < 2; e++) {
                    float t = Ts[pr * TST + il0 + e];
                    float u0 = 1.0f, u1 = t;
                    vals[e * 8 + 0] = f32_to_tf32(t);
#pragma unroll
                    for (int d = 2; d <= 8; d++) {
                        float u2 = fmaf(2.0f * t, u1, -u0);
                        vals[e * 8 + d - 1] = f32_to_tf32(u2);
                        u0 = u1; u1 = u2;
                    }
                }
                uint4* dstv = (uint4*)&As[s][pr * AST + ph * 16];
#pragma unroll
                for (int q = 0; q < 4; q++)
                    dstv[q] = make_uint4(vals[4*q], vals[4*q+1], vals[4*q+2], vals[4*q+3]);
            }

            // ---- B[s] landed; stage s^1 consumers all past ----
            cp_wait0();
            __syncthreads();

            // ---- prefetch B[j+1] into stage s^1 ----
            if (j + 1 < NITER) {
                const float* src = g_Bt + (size_t)(n0 + pr) * KD2 + (j + 1) * KC + ph * 16;
                uint32_t dst = smem_u32(&Bs[s ^ 1][pr * BST + ph * 16]);
#pragma unroll
                for (int q = 0; q < 4; q++) cp_async16(dst + q * 16, src + q * 4);
            }
            cp_commit();

            // ---- consume: 64 MMAs per warp ----
            const uint32_t* A_ = As[s];
            const uint32_t* B_ = Bs[s];
#pragma unroll
            for (int ks = 0; ks < 4; ks++) {
                const int kk = ks * 8;
                uint32_t a[4][4];
#pragma unroll
                for (int mf = 0; mf < 4; mf++) {
                    int r0 = warp_m * 64 + mf * 16 + gid;
                    a[mf][0] = A_[r0 * AST + kk + tg];
                    a[mf][1] = A_[(r0 + 8) * AST + kk + tg];
                    a[mf][2] = A_[r0 * AST + kk + tg + 4];
                    a[mf][3] = A_[(r0 + 8) * AST + kk + tg + 4];
                }
#pragma unroll
                for (int nf = 0; nf < 4; nf++) {
                    int nn = warp_n * 32 + nf * 8 + gid;
                    uint32_t b[2];
                    b[0] = B_[nn * BST + kk + tg];
                    b[1] = B_[nn * BST + kk + tg + 4];
#pragma unroll
                    for (int mf = 0; mf < 4; mf++)
                        mma8(acc[mf][nf], a[mf], b);
                }
            }
        }
    }

    // ---- epilogue: add T0 bias, write D ----
#pragma unroll
    for (int nf = 0; nf < 4; nf++) {
        int col = n0 + warp_n * 32 + nf * 8 + tg * 2;
        float2 bv = *(const float2*)&g_bias[col];
#pragma unroll
        for (int mf = 0; mf < 4; mf++) {
            int row = m0 + warp_m * 64 + mf * 16 + gid;
            float2* p0 = (float2*)(out + (size_t)row * OUTDIM + col);
            float2* p1 = (float2*)(out + (size_t)(row + 8) * OUTDIM + col);
            *p0 = make_float2(acc[mf][nf][0] + bv.x, acc[mf][nf][1] + bv.y);
            *p1 = make_float2(acc[mf][nf][2] + bv.x, acc[mf][nf][3] + bv.y);
        }
    }
}

// ============================ host launch ==============================
extern "C" void kernel_launch(void* const* d_in, const int* in_sizes, int n_in,
                              void* d_out, int out_size) {
    const float* x;
    const float* C;
    if (in_sizes[0] == BATCH * INDIM) { x = (const float*)d_in[0]; C = (const float*)d_in[1]; }
    else                              { x = (const float*)d_in[1]; C = (const float*)d_in[0]; }
    float* out = (float*)d_out;

    prep_t_kernel<<<(BATCH * INDIM) / (256 * 4), 256>>>(x);
    prep_Bt_kernel<<<(INDIM * OUTDIM) / 256, 256>>>(C);
    prep_bias_kernel<<<OUTDIM, 256>>>(C);

    dim3 grid(BATCH / TM, OUTDIM / TN, 1);   // 64 x 8 = 512 CTAs, 2 per SM
    cheby_gemm_kernel<<<grid, NTHREADS>>>(out);
}